// round 1
// baseline (speedup 1.0000x reference)
#include <cuda_runtime.h>
#include <math.h>

#define Bn 32
#define Tn 1024
#define Dn 512
#define Gn 256
#define En 8
#define Vn 8192

#define BM 64
#define BN 64
#define BK 16
#define TM 4
#define TN 4
#define NTHREADS 256

// Scratch (no cudaMalloc allowed)
__device__ float g_sumexp[Bn * Tn];
__device__ float g_tgt[Bn * Tn];
__device__ int   g_assign[Bn];
__device__ float g_ce[Bn];

// ---------------------------------------------------------------------------
// Router: logits = gate @ Wg + bg ; softmax -> probs ; argmax -> assignments.
// Also zeroes the whole output buffer and the sumexp accumulator.
// 1 block, 256 threads.
// ---------------------------------------------------------------------------
__global__ void router_kernel(const float* __restrict__ gate,
                              const float* __restrict__ Wg,
                              const float* __restrict__ bg,
                              float* __restrict__ out, int out_size)
{
    int tid = threadIdx.x;

    // zero output buffer (poisoned to 0xAA by harness)
    for (int i = tid; i < out_size; i += NTHREADS) out[i] = 0.0f;

    // zero per-token sum-exp accumulator
    for (int i = tid; i < Bn * Tn; i += NTHREADS) g_sumexp[i] = 0.0f;

    __shared__ float logits[Bn][En];

    // 32 x 8 = 256 threads: one logit each
    int i = tid / En;   // sample
    int j = tid % En;   // expert
    float acc = bg[j];
    const float* grow = gate + i * Gn;
    #pragma unroll 4
    for (int g = 0; g < Gn; g++) acc += grow[g] * Wg[g * En + j];
    logits[i][j] = acc;
    __syncthreads();

    if (tid < Bn) {
        float mx = logits[tid][0];
        int am = 0;
        #pragma unroll
        for (int e = 1; e < En; e++) {
            float v = logits[tid][e];
            if (v > mx) { mx = v; am = e; }   // strict > keeps first occurrence
        }
        float ex[En];
        float s = 0.0f;
        #pragma unroll
        for (int e = 0; e < En; e++) { ex[e] = expf(logits[tid][e] - mx); s += ex[e]; }
        float inv = 1.0f / s;
        #pragma unroll
        for (int e = 0; e < En; e++) out[1 + Bn + tid * En + e] = ex[e] * inv;
        out[1 + tid] = (float)am;
        g_assign[tid] = am;
    }
}

// ---------------------------------------------------------------------------
// Fused GEMM + exp-sum + target-logit capture.
// Tile: 64 tokens x 64 vocab, K = 512 swept in chunks of 16.
// grid = (V/BN, T/BM, B). Each block: C = X_tile @ W_tile (+bias),
// accumulates sum(exp(logit)) per token via one atomicAdd per token row,
// and writes the target logit when its vocab column lands in this tile.
// ---------------------------------------------------------------------------
__global__ void __launch_bounds__(NTHREADS)
gemm_ce_kernel(const float* __restrict__ X,        // [B,T,D]
               const float* __restrict__ We,       // [E,D,V]
               const float* __restrict__ be,       // [E,V]
               const long long* __restrict__ tgt)  // [B,T] int64
{
    const int vt = blockIdx.x;           // vocab tile
    const int tt = blockIdx.y;           // token tile
    const int b  = blockIdx.z;           // sample
    const int e  = g_assign[b];

    const int v0 = vt * BN;
    const int t0 = tt * BM;

    const float* A = X  + (size_t)b * Tn * Dn + (size_t)t0 * Dn;
    const float* W = We + (size_t)e * Dn * Vn + v0;

    __shared__ float As[BK][BM];   // transposed: As[k][m]
    __shared__ float Bs[BK][BN];   // Bs[k][n]

    const int tid = threadIdx.x;
    const int tx = tid & 15;       // 0..15 -> vocab
    const int ty = tid >> 4;       // 0..15 -> token

    // load indices
    const int arow = tid >> 2;            // 0..63 token row
    const int akq  = (tid & 3) * 4;       // k quad
    const int brow = tid >> 4;            // 0..15 k row
    const int bvq  = (tid & 15) * 4;      // vocab quad

    float acc[TM][TN];
    #pragma unroll
    for (int m = 0; m < TM; m++)
        #pragma unroll
        for (int n = 0; n < TN; n++) acc[m][n] = 0.0f;

    for (int k0 = 0; k0 < Dn; k0 += BK) {
        float4 a4 = *(const float4*)(A + (size_t)arow * Dn + k0 + akq);
        float4 b4 = *(const float4*)(W + (size_t)(k0 + brow) * Vn + bvq);
        __syncthreads();               // previous compute done before overwrite
        As[akq + 0][arow] = a4.x;
        As[akq + 1][arow] = a4.y;
        As[akq + 2][arow] = a4.z;
        As[akq + 3][arow] = a4.w;
        *(float4*)&Bs[brow][bvq] = b4;
        __syncthreads();

        #pragma unroll
        for (int kk = 0; kk < BK; kk++) {
            float a[TM], bb[TN];
            *(float4*)a  = *(const float4*)&As[kk][ty * TM];
            *(float4*)bb = *(const float4*)&Bs[kk][tx * TN];
            #pragma unroll
            for (int m = 0; m < TM; m++)
                #pragma unroll
                for (int n = 0; n < TN; n++)
                    acc[m][n] = fmaf(a[m], bb[n], acc[m][n]);
        }
    }

    // ---- epilogue: bias, exp-sum per token row, target logit capture ----
    float rowsum[TM];
    float bias[TN];
    #pragma unroll
    for (int n = 0; n < TN; n++) bias[n] = be[(size_t)e * Vn + v0 + tx * TN + n];

    #pragma unroll
    for (int m = 0; m < TM; m++) {
        const int t = t0 + ty * TM + m;
        const long long tg = tgt[(size_t)b * Tn + t];
        float s = 0.0f;
        #pragma unroll
        for (int n = 0; n < TN; n++) {
            const int v = v0 + tx * TN + n;
            const float logit = acc[m][n] + bias[n];
            s += __expf(logit);
            if ((long long)v == tg) g_tgt[(size_t)b * Tn + t] = logit;
        }
        rowsum[m] = s;
    }

    // reduce rowsum across the 16 vocab-threads per token row (reuse As memory)
    __syncthreads();                     // everyone past compute before reuse
    float (*S)[16] = (float (*)[16])&As[0][0];   // [64][16]
    #pragma unroll
    for (int m = 0; m < TM; m++) S[ty * TM + m][tx] = rowsum[m];
    __syncthreads();

    if (tid < BM) {
        float s = 0.0f;
        #pragma unroll
        for (int q = 0; q < 16; q++) s += S[tid][q];
        atomicAdd(&g_sumexp[(size_t)b * Tn + t0 + tid], s);
    }
}

// ---------------------------------------------------------------------------
// Per-sample CE: ce[b] = mean_t( log(sumexp) - target_logit )
// ---------------------------------------------------------------------------
__global__ void ce_reduce_kernel()
{
    const int b = blockIdx.x;
    const int tid = threadIdx.x;
    float s = 0.0f;
    for (int t = tid; t < Tn; t += NTHREADS) {
        const int idx = b * Tn + t;
        s += logf(g_sumexp[idx]) - g_tgt[idx];
    }
    __shared__ float red[NTHREADS];
    red[tid] = s;
    __syncthreads();
    for (int off = NTHREADS / 2; off > 0; off >>= 1) {
        if (tid < off) red[tid] += red[tid + off];
        __syncthreads();
    }
    if (tid == 0) g_ce[b] = red[0] / (float)Tn;
}

// ---------------------------------------------------------------------------
// total_loss = sum_e mean over samples assigned to e
// ---------------------------------------------------------------------------
__global__ void final_kernel(float* __restrict__ out)
{
    if (threadIdx.x == 0) {
        float sums[En];
        float cnt[En];
        #pragma unroll
        for (int e = 0; e < En; e++) { sums[e] = 0.0f; cnt[e] = 0.0f; }
        for (int b = 0; b < Bn; b++) {
            sums[g_assign[b]] += g_ce[b];
            cnt[g_assign[b]]  += 1.0f;
        }
        float tot = 0.0f;
        #pragma unroll
        for (int e = 0; e < En; e++)
            if (cnt[e] > 0.0f) tot += sums[e] / cnt[e];
        out[0] = tot;
    }
}

extern "C" void kernel_launch(void* const* d_in, const int* in_sizes, int n_in,
                              void* d_out, int out_size)
{
    const float*     gate = (const float*)d_in[0];      // [B,G]
    const float*     X    = (const float*)d_in[1];      // [B,T,D]
    const float*     Wg   = (const float*)d_in[2];      // [G,E]
    const float*     bg   = (const float*)d_in[3];      // [E]
    const float*     We   = (const float*)d_in[4];      // [E,D,V]
    const float*     be   = (const float*)d_in[5];      // [E,V]
    const long long* tgt  = (const long long*)d_in[6];  // [B,T]
    float* out = (float*)d_out;

    router_kernel<<<1, NTHREADS>>>(gate, Wg, bg, out, out_size);

    dim3 grid(Vn / BN, Tn / BM, Bn);
    gemm_ce_kernel<<<grid, NTHREADS>>>(X, We, be, tgt);

    ce_reduce_kernel<<<Bn, NTHREADS>>>();
    final_kernel<<<1, 32>>>(out);
}

// round 3
// speedup vs baseline: 5.9205x; 5.9205x over previous
#include <cuda_runtime.h>
#include <cuda_bf16.h>
#include <math.h>
#include <stdint.h>

#define Bn 32
#define Tn 1024
#define Dn 512
#define Gn 256
#define En 8
#define Vn 8192

#define BM 128
#define BN 256
#define BK 32
#define GTHREADS 512
#define NTHREADS 256

// smem strides (bytes), padded for conflict-free ldmatrix
#define A_STRIDE 80      // 32 bf16 = 64B + 16B pad  (5 mod 8 step)
#define B_STRIDE 528     // 256 bf16 = 512B + 16B pad (33 mod 8 -> 1 step)
#define A_BYTES (BM * A_STRIDE)          // 10240
#define B_BYTES (BK * B_STRIDE)          // 16896
#define STAGE_BYTES (A_BYTES + B_BYTES)  // 27136
#define NSTAGES 3
#define SMEM_BYTES (NSTAGES * STAGE_BYTES)  // 81408

// ---------------- scratch (no cudaMalloc allowed) ----------------
__device__ __nv_bfloat16 g_Xbf[(size_t)Bn * Tn * Dn];   // [B,T,D]
__device__ __nv_bfloat16 g_Wbf[(size_t)En * Dn * Vn];   // [E,D,V] (same layout as input)
__device__ float g_sumexp[Bn * Tn];
__device__ float g_tgt[Bn * Tn];
__device__ int   g_assign[Bn];
__device__ float g_ce[Bn];

// ---------------- helpers ----------------
__device__ __forceinline__ uint32_t s2u(const void* p) {
    uint32_t a;
    asm("{ .reg .u64 t; cvta.to.shared.u64 t, %1; cvt.u32.u64 %0, t; }" : "=r"(a) : "l"(p));
    return a;
}
__device__ __forceinline__ void cp16(uint32_t dst, const void* src) {
    asm volatile("cp.async.cg.shared.global [%0], [%1], 16;" :: "r"(dst), "l"(src) : "memory");
}
__device__ __forceinline__ void cp_commit() { asm volatile("cp.async.commit_group;" ::: "memory"); }

__device__ __forceinline__ void ldsm_x4(uint32_t& r0, uint32_t& r1, uint32_t& r2, uint32_t& r3, uint32_t a) {
    asm volatile("ldmatrix.sync.aligned.m8n8.x4.shared.b16 {%0,%1,%2,%3}, [%4];"
                 : "=r"(r0), "=r"(r1), "=r"(r2), "=r"(r3) : "r"(a));
}
__device__ __forceinline__ void ldsm_x2t(uint32_t& r0, uint32_t& r1, uint32_t a) {
    asm volatile("ldmatrix.sync.aligned.m8n8.x2.trans.shared.b16 {%0,%1}, [%2];"
                 : "=r"(r0), "=r"(r1) : "r"(a));
}
__device__ __forceinline__ void mma_bf16(float* d, const uint32_t* a, const uint32_t* b) {
    asm volatile("mma.sync.aligned.m16n8k16.row.col.f32.bf16.bf16.f32 "
                 "{%0,%1,%2,%3}, {%4,%5,%6,%7}, {%8,%9}, {%0,%1,%2,%3};"
                 : "+f"(d[0]), "+f"(d[1]), "+f"(d[2]), "+f"(d[3])
                 : "r"(a[0]), "r"(a[1]), "r"(a[2]), "r"(a[3]), "r"(b[0]), "r"(b[1]));
}

// fast exp on fma/alu pipes (no MUFU)
__device__ __forceinline__ float fexp(float x) {
    float j = fmaf(x, 1.4426950408889634f, 12582912.0f);
    int ji = __float_as_int(j);
    j -= 12582912.0f;
    float f = fmaf(j, -0.693359375f, x);
    f = fmaf(j, 2.12194440e-4f, f);
    float p = 1.9875691500e-4f;
    p = fmaf(p, f, 1.3981999507e-3f);
    p = fmaf(p, f, 8.3334519073e-3f);
    p = fmaf(p, f, 4.1665795894e-2f);
    p = fmaf(p, f, 1.6666665459e-1f);
    p = fmaf(p, f, 5.0000001201e-1f);
    float z = f * f;
    float r = fmaf(p, z, f) + 1.0f;
    return __int_as_float(__float_as_int(r) + (ji << 23));
}

// ---------------- conversion kernels (elementwise fp32 -> bf16) ----------------
__global__ void convert_x_kernel(const float4* __restrict__ X) {
    size_t i = (size_t)blockIdx.x * blockDim.x + threadIdx.x;
    float4 v = X[i];
    __nv_bfloat162* o = (__nv_bfloat162*)g_Xbf;
    o[2 * i + 0] = __nv_bfloat162(__float2bfloat16(v.x), __float2bfloat16(v.y));
    o[2 * i + 1] = __nv_bfloat162(__float2bfloat16(v.z), __float2bfloat16(v.w));
}
__global__ void convert_w_kernel(const float4* __restrict__ W) {
    size_t i = (size_t)blockIdx.x * blockDim.x + threadIdx.x;
    float4 v = W[i];
    __nv_bfloat162* o = (__nv_bfloat162*)g_Wbf;
    o[2 * i + 0] = __nv_bfloat162(__float2bfloat16(v.x), __float2bfloat16(v.y));
    o[2 * i + 1] = __nv_bfloat162(__float2bfloat16(v.z), __float2bfloat16(v.w));
}

// ---------------- router ----------------
__global__ void router_kernel(const float* __restrict__ gate,
                              const float* __restrict__ Wg,
                              const float* __restrict__ bg,
                              float* __restrict__ out, int out_size)
{
    int tid = threadIdx.x;
    for (int i = tid; i < out_size; i += NTHREADS) out[i] = 0.0f;
    for (int i = tid; i < Bn * Tn; i += NTHREADS) g_sumexp[i] = 0.0f;

    __shared__ float logits[Bn][En];
    int i = tid / En, j = tid % En;
    float acc = bg[j];
    const float* grow = gate + i * Gn;
    #pragma unroll 4
    for (int g = 0; g < Gn; g++) acc += grow[g] * Wg[g * En + j];
    logits[i][j] = acc;
    __syncthreads();

    if (tid < Bn) {
        float mx = logits[tid][0];
        int am = 0;
        #pragma unroll
        for (int e = 1; e < En; e++) {
            float v = logits[tid][e];
            if (v > mx) { mx = v; am = e; }
        }
        float ex[En], s = 0.0f;
        #pragma unroll
        for (int e = 0; e < En; e++) { ex[e] = expf(logits[tid][e] - mx); s += ex[e]; }
        float inv = 1.0f / s;
        #pragma unroll
        for (int e = 0; e < En; e++) out[1 + Bn + tid * En + e] = ex[e] * inv;
        out[1 + tid] = (float)am;
        g_assign[tid] = am;
    }
}

// ---------------- fused HMMA GEMM + CE epilogue ----------------
// grid (V/BN=32, T/BM=8, B=32), 512 threads, warp grid 2(M) x 8(N), warp tile 64x32.
__device__ __forceinline__ void load_stage(uint32_t sA, uint32_t sB,
                                           const __nv_bfloat16* Ag,
                                           const __nv_bfloat16* Bg,
                                           int k0, int tid)
{
    // A: 128 rows x 32 bf16 (64B) = 512 x 16B segs; 512 threads -> 1 each
    {
        int row = tid >> 2, j = tid & 3;
        cp16(sA + (uint32_t)(row * A_STRIDE + j * 16),
             Ag + (size_t)row * Dn + k0 + j * 8);
    }
    // B: 32 k-rows x 256 bf16 (512B) = 1024 x 16B segs; 2 each
    #pragma unroll
    for (int i = 0; i < 2; i++) {
        int s = tid + i * GTHREADS;
        int kr = s >> 5, j = s & 31;
        cp16(sB + (uint32_t)(kr * B_STRIDE + j * 16),
             Bg + (size_t)kr * Vn + j * 8);
    }
}

__global__ void __launch_bounds__(GTHREADS, 1)
gemm_ce_kernel(const float* __restrict__ be, const long long* __restrict__ tgt)
{
    extern __shared__ char smem[];
    const uint32_t sbase = s2u(smem);
    const int tid  = threadIdx.x;
    const int wid  = tid >> 5;
    const int lane = tid & 31;
    const int wm   = wid >> 3;    // 0..1
    const int wn   = wid & 7;     // 0..7

    const int vt = blockIdx.x, tt = blockIdx.y, b = blockIdx.z;
    const int e  = g_assign[b];
    const int v0 = vt * BN;
    const int t0 = tt * BM;

    const __nv_bfloat16* Ag = g_Xbf + ((size_t)b * Tn + t0) * Dn;
    const __nv_bfloat16* Bg = g_Wbf + (size_t)e * Dn * Vn + v0;   // [d][v] rows

    float acc[4][4][4];
    #pragma unroll
    for (int mt = 0; mt < 4; mt++)
        #pragma unroll
        for (int nt = 0; nt < 4; nt++)
            #pragma unroll
            for (int r = 0; r < 4; r++) acc[mt][nt][r] = 0.0f;

    // ldmatrix base addresses (per-lane)
    // A: row = wm*64 + mt*16 + (lane&15), khalf = lane>>4
    const uint32_t a_lane_off = (uint32_t)((lane & 15) * A_STRIDE + (lane >> 4) * 16);
    // B(trans): krow = kt*16 + (lane&15), col bytes = wn*64 + nt*16
    const uint32_t b_lane_off = (uint32_t)((lane & 15) * B_STRIDE + wn * 64);

    uint32_t sA[NSTAGES], sB[NSTAGES];
    #pragma unroll
    for (int s = 0; s < NSTAGES; s++) {
        sA[s] = sbase + s * STAGE_BYTES;
        sB[s] = sbase + s * STAGE_BYTES + A_BYTES;
    }

    load_stage(sA[0], sB[0], Ag, Bg, 0, tid);  cp_commit();
    load_stage(sA[1], sB[1], Ag, Bg, BK, tid); cp_commit();

    const int NCHUNK = Dn / BK;   // 16
    #pragma unroll 1
    for (int c = 0; c < NCHUNK; c++) {
        const int s = c % NSTAGES;
        if (c < NCHUNK - 1) asm volatile("cp.async.wait_group 1;" ::: "memory");
        else                asm volatile("cp.async.wait_group 0;" ::: "memory");
        __syncthreads();

        if (c + 2 < NCHUNK) {
            load_stage(sA[(c + 2) % NSTAGES], sB[(c + 2) % NSTAGES], Ag, Bg, (c + 2) * BK, tid);
            cp_commit();
        }

        const uint32_t aBase = sA[s] + a_lane_off + (uint32_t)(wm * 64 * A_STRIDE);
        const uint32_t bBase = sB[s] + b_lane_off;

        #pragma unroll
        for (int kt = 0; kt < 2; kt++) {
            uint32_t af[4][4], bf[4][2];
            #pragma unroll
            for (int mt = 0; mt < 4; mt++)
                ldsm_x4(af[mt][0], af[mt][1], af[mt][2], af[mt][3],
                        aBase + (uint32_t)(mt * 16 * A_STRIDE + kt * 32));
            #pragma unroll
            for (int nt = 0; nt < 4; nt++)
                ldsm_x2t(bf[nt][0], bf[nt][1],
                         bBase + (uint32_t)(kt * 16 * B_STRIDE + nt * 16));
            #pragma unroll
            for (int mt = 0; mt < 4; mt++)
                #pragma unroll
                for (int nt = 0; nt < 4; nt++)
                    mma_bf16(acc[mt][nt], af[mt], bf[nt]);
        }
    }

    // ---- epilogue ----
    const int c0 = (lane & 3) * 2;
    const int r0 = lane >> 2;
    const float* bias_base = be + (size_t)e * Vn + v0 + wn * 32 + c0;

    float bias0[4], bias1[4];
    #pragma unroll
    for (int nt = 0; nt < 4; nt++) {
        bias0[nt] = bias_base[nt * 8];
        bias1[nt] = bias_base[nt * 8 + 1];
    }

    #pragma unroll
    for (int mt = 0; mt < 4; mt++) {
        const int row0 = t0 + wm * 64 + mt * 16 + r0;
        const int row1 = row0 + 8;
        const long long tg0 = tgt[(size_t)b * Tn + row0];
        const long long tg1 = tgt[(size_t)b * Tn + row1];
        float s0 = 0.0f, s1 = 0.0f;
        #pragma unroll
        for (int nt = 0; nt < 4; nt++) {
            const int v = v0 + wn * 32 + nt * 8 + c0;
            float l00 = acc[mt][nt][0] + bias0[nt];
            float l01 = acc[mt][nt][1] + bias1[nt];
            float l10 = acc[mt][nt][2] + bias0[nt];
            float l11 = acc[mt][nt][3] + bias1[nt];
            s0 += fexp(l00) + fexp(l01);
            s1 += fexp(l10) + fexp(l11);
            if ((long long)v     == tg0) g_tgt[(size_t)b * Tn + row0] = l00;
            if ((long long)(v+1) == tg0) g_tgt[(size_t)b * Tn + row0] = l01;
            if ((long long)v     == tg1) g_tgt[(size_t)b * Tn + row1] = l10;
            if ((long long)(v+1) == tg1) g_tgt[(size_t)b * Tn + row1] = l11;
        }
        s0 += __shfl_xor_sync(0xffffffffu, s0, 1);
        s0 += __shfl_xor_sync(0xffffffffu, s0, 2);
        s1 += __shfl_xor_sync(0xffffffffu, s1, 1);
        s1 += __shfl_xor_sync(0xffffffffu, s1, 2);
        if ((lane & 3) == 0) {
            atomicAdd(&g_sumexp[(size_t)b * Tn + row0], s0);
            atomicAdd(&g_sumexp[(size_t)b * Tn + row1], s1);
        }
    }
}

// ---------------- CE reductions ----------------
__global__ void ce_reduce_kernel()
{
    const int b = blockIdx.x;
    const int tid = threadIdx.x;
    float s = 0.0f;
    for (int t = tid; t < Tn; t += NTHREADS) {
        const int idx = b * Tn + t;
        s += logf(g_sumexp[idx]) - g_tgt[idx];
    }
    __shared__ float red[NTHREADS];
    red[tid] = s;
    __syncthreads();
    for (int off = NTHREADS / 2; off > 0; off >>= 1) {
        if (tid < off) red[tid] += red[tid + off];
        __syncthreads();
    }
    if (tid == 0) g_ce[b] = red[0] / (float)Tn;
}

__global__ void final_kernel(float* __restrict__ out)
{
    if (threadIdx.x == 0) {
        float sums[En], cnt[En];
        #pragma unroll
        for (int e = 0; e < En; e++) { sums[e] = 0.0f; cnt[e] = 0.0f; }
        for (int b = 0; b < Bn; b++) {
            sums[g_assign[b]] += g_ce[b];
            cnt[g_assign[b]]  += 1.0f;
        }
        float tot = 0.0f;
        #pragma unroll
        for (int e = 0; e < En; e++)
            if (cnt[e] > 0.0f) tot += sums[e] / cnt[e];
        out[0] = tot;
    }
}

// ---------------- launcher ----------------
extern "C" void kernel_launch(void* const* d_in, const int* in_sizes, int n_in,
                              void* d_out, int out_size)
{
    const float*     gate = (const float*)d_in[0];
    const float*     X    = (const float*)d_in[1];
    const float*     Wg   = (const float*)d_in[2];
    const float*     bg   = (const float*)d_in[3];
    const float*     We   = (const float*)d_in[4];
    const float*     be   = (const float*)d_in[5];
    const long long* tgt  = (const long long*)d_in[6];
    float* out = (float*)d_out;

    cudaFuncSetAttribute(gemm_ce_kernel, cudaFuncAttributeMaxDynamicSharedMemorySize, SMEM_BYTES);

    convert_x_kernel<<<((size_t)Bn * Tn * Dn / 4) / 256, 256>>>((const float4*)X);
    convert_w_kernel<<<((size_t)En * Dn * Vn / 4) / 256, 256>>>((const float4*)We);

    router_kernel<<<1, NTHREADS>>>(gate, Wg, bg, out, out_size);

    dim3 grid(Vn / BN, Tn / BM, Bn);
    gemm_ce_kernel<<<grid, GTHREADS, SMEM_BYTES>>>(be, tgt);

    ce_reduce_kernel<<<Bn, NTHREADS>>>();
    final_kernel<<<1, 32>>>(out);
}

// round 4
// speedup vs baseline: 7.5104x; 1.2685x over previous
#include <cuda_runtime.h>
#include <cuda_bf16.h>
#include <math.h>
#include <stdint.h>

#define Bn 32
#define Tn 1024
#define Dn 512
#define Gn 256
#define En 8
#define Vn 8192

#define BM 128
#define BN 128
#define BK 32
#define GTHREADS 256
#define NTHREADS 256

// smem strides (bytes), padded for conflict-free ldmatrix
#define A_STRIDE 80      // 32 bf16 = 64B + 16B pad
#define B_STRIDE 272     // 128 bf16 = 256B + 16B pad
#define A_BYTES (BM * A_STRIDE)          // 10240
#define B_BYTES (BK * B_STRIDE)          // 8704
#define STAGE_BYTES (A_BYTES + B_BYTES)  // 18944
#define NSTAGES 4
#define SMEM_BYTES (NSTAGES * STAGE_BYTES)  // 75776

// ---------------- scratch (no cudaMalloc allowed) ----------------
__device__ __nv_bfloat16 g_Xbf[(size_t)Bn * Tn * Dn];   // [B,T,D]
__device__ __nv_bfloat16 g_Wbf[(size_t)En * Dn * Vn];   // [E,D,V]
__device__ float g_sumexp[Bn * Tn];
__device__ float g_tgt[Bn * Tn];
__device__ int   g_assign[Bn];
__device__ float g_ce[Bn];

// ---------------- helpers ----------------
__device__ __forceinline__ uint32_t s2u(const void* p) {
    uint32_t a;
    asm("{ .reg .u64 t; cvta.to.shared.u64 t, %1; cvt.u32.u64 %0, t; }" : "=r"(a) : "l"(p));
    return a;
}
__device__ __forceinline__ void cp16(uint32_t dst, const void* src) {
    asm volatile("cp.async.cg.shared.global [%0], [%1], 16;" :: "r"(dst), "l"(src) : "memory");
}
__device__ __forceinline__ void cp_commit() { asm volatile("cp.async.commit_group;" ::: "memory"); }

__device__ __forceinline__ void ldsm_x4(uint32_t& r0, uint32_t& r1, uint32_t& r2, uint32_t& r3, uint32_t a) {
    asm volatile("ldmatrix.sync.aligned.m8n8.x4.shared.b16 {%0,%1,%2,%3}, [%4];"
                 : "=r"(r0), "=r"(r1), "=r"(r2), "=r"(r3) : "r"(a));
}
__device__ __forceinline__ void ldsm_x4t(uint32_t& r0, uint32_t& r1, uint32_t& r2, uint32_t& r3, uint32_t a) {
    asm volatile("ldmatrix.sync.aligned.m8n8.x4.trans.shared.b16 {%0,%1,%2,%3}, [%4];"
                 : "=r"(r0), "=r"(r1), "=r"(r2), "=r"(r3) : "r"(a));
}
__device__ __forceinline__ void mma_bf16(float* d, const uint32_t* a, const uint32_t* b) {
    asm volatile("mma.sync.aligned.m16n8k16.row.col.f32.bf16.bf16.f32 "
                 "{%0,%1,%2,%3}, {%4,%5,%6,%7}, {%8,%9}, {%0,%1,%2,%3};"
                 : "+f"(d[0]), "+f"(d[1]), "+f"(d[2]), "+f"(d[3])
                 : "r"(a[0]), "r"(a[1]), "r"(a[2]), "r"(a[3]), "r"(b[0]), "r"(b[1]));
}

// ---------------- conversion kernels ----------------
__global__ void convert_x_kernel(const float4* __restrict__ X) {
    size_t i = (size_t)blockIdx.x * blockDim.x + threadIdx.x;
    float4 v = X[i];
    __nv_bfloat162* o = (__nv_bfloat162*)g_Xbf;
    o[2 * i + 0] = __nv_bfloat162(__float2bfloat16(v.x), __float2bfloat16(v.y));
    o[2 * i + 1] = __nv_bfloat162(__float2bfloat16(v.z), __float2bfloat16(v.w));
}
__global__ void convert_w_kernel(const float4* __restrict__ W) {
    size_t i = (size_t)blockIdx.x * blockDim.x + threadIdx.x;
    float4 v = W[i];
    __nv_bfloat162* o = (__nv_bfloat162*)g_Wbf;
    o[2 * i + 0] = __nv_bfloat162(__float2bfloat16(v.x), __float2bfloat16(v.y));
    o[2 * i + 1] = __nv_bfloat162(__float2bfloat16(v.z), __float2bfloat16(v.w));
}

// ---------------- router ----------------
__global__ void router_kernel(const float* __restrict__ gate,
                              const float* __restrict__ Wg,
                              const float* __restrict__ bg,
                              float* __restrict__ out, int out_size)
{
    int tid = threadIdx.x;
    for (int i = tid; i < out_size; i += NTHREADS) out[i] = 0.0f;
    for (int i = tid; i < Bn * Tn; i += NTHREADS) g_sumexp[i] = 0.0f;

    __shared__ float logits[Bn][En];
    int i = tid / En, j = tid % En;
    float acc = bg[j];
    const float* grow = gate + i * Gn;
    #pragma unroll 4
    for (int g = 0; g < Gn; g++) acc += grow[g] * Wg[g * En + j];
    logits[i][j] = acc;
    __syncthreads();

    if (tid < Bn) {
        float mx = logits[tid][0];
        int am = 0;
        #pragma unroll
        for (int e = 1; e < En; e++) {
            float v = logits[tid][e];
            if (v > mx) { mx = v; am = e; }
        }
        float ex[En], s = 0.0f;
        #pragma unroll
        for (int e = 0; e < En; e++) { ex[e] = expf(logits[tid][e] - mx); s += ex[e]; }
        float inv = 1.0f / s;
        #pragma unroll
        for (int e = 0; e < En; e++) out[1 + Bn + tid * En + e] = ex[e] * inv;
        out[1 + tid] = (float)am;
        g_assign[tid] = am;
    }
}

// ---------------- fused HMMA GEMM + CE epilogue ----------------
// grid (V/BN=64, T/BM=8, B=32), 256 threads, 8 warps: warp grid 2(M) x 4(N),
// warp tile 64x32, 2 CTAs/SM.
__device__ __forceinline__ void load_stage(uint32_t sA, uint32_t sB,
                                           const __nv_bfloat16* Ag,
                                           const __nv_bfloat16* Bg,
                                           int k0, int tid)
{
    // A: 128 rows x 32 bf16 (64B) = 512 x 16B segs; 2 per thread
    #pragma unroll
    for (int i = 0; i < 2; i++) {
        int s = tid + i * GTHREADS;
        int row = s >> 2, j = s & 3;
        cp16(sA + (uint32_t)(row * A_STRIDE + j * 16),
             Ag + (size_t)row * Dn + k0 + j * 8);
    }
    // B: 32 k-rows x 128 bf16 (256B) = 512 x 16B segs; 2 per thread
    #pragma unroll
    for (int i = 0; i < 2; i++) {
        int s = tid + i * GTHREADS;
        int kr = s >> 4, j = s & 15;
        cp16(sB + (uint32_t)(kr * B_STRIDE + j * 16),
             Bg + (size_t)(k0 + kr) * Vn + j * 8);
    }
}

__global__ void __launch_bounds__(GTHREADS, 2)
gemm_ce_kernel(const float* __restrict__ be, const long long* __restrict__ tgt)
{
    extern __shared__ char smem[];
    const uint32_t sbase = s2u(smem);
    const int tid  = threadIdx.x;
    const int wid  = tid >> 5;
    const int lane = tid & 31;
    const int wm   = wid >> 2;    // 0..1
    const int wn   = wid & 3;     // 0..3

    const int vt = blockIdx.x, tt = blockIdx.y, b = blockIdx.z;
    const int e  = g_assign[b];
    const int v0 = vt * BN;
    const int t0 = tt * BM;

    const __nv_bfloat16* Ag = g_Xbf + ((size_t)b * Tn + t0) * Dn;
    const __nv_bfloat16* Bg = g_Wbf + (size_t)e * Dn * Vn + v0;   // rows = d

    float acc[4][4][4];
    #pragma unroll
    for (int mt = 0; mt < 4; mt++)
        #pragma unroll
        for (int nt = 0; nt < 4; nt++)
            #pragma unroll
            for (int r = 0; r < 4; r++) acc[mt][nt][r] = 0.0f;

    // per-lane ldmatrix offsets
    const uint32_t a_lane_off = (uint32_t)((lane & 15) * A_STRIDE + (lane >> 4) * 16)
                              + (uint32_t)(wm * 64 * A_STRIDE);
    // B x4.trans: k_row = lane&15, col8-group = lane>>4
    const uint32_t b_lane_off = (uint32_t)((lane & 15) * B_STRIDE
                              + (wn * 32 + (lane >> 4) * 8) * 2);

    uint32_t sA[NSTAGES], sB[NSTAGES];
    #pragma unroll
    for (int s = 0; s < NSTAGES; s++) {
        sA[s] = sbase + s * STAGE_BYTES;
        sB[s] = sbase + s * STAGE_BYTES + A_BYTES;
    }

    load_stage(sA[0], sB[0], Ag, Bg, 0, tid);      cp_commit();
    load_stage(sA[1], sB[1], Ag, Bg, BK, tid);     cp_commit();
    load_stage(sA[2], sB[2], Ag, Bg, 2 * BK, tid); cp_commit();

    const int NCHUNK = Dn / BK;   // 16
    #pragma unroll 1
    for (int c = 0; c < NCHUNK; c++) {
        const int s = c & 3;
        if (c < NCHUNK - 2)      asm volatile("cp.async.wait_group 2;" ::: "memory");
        else if (c == NCHUNK - 2) asm volatile("cp.async.wait_group 1;" ::: "memory");
        else                      asm volatile("cp.async.wait_group 0;" ::: "memory");
        __syncthreads();

        if (c + 3 < NCHUNK) {
            load_stage(sA[(c + 3) & 3], sB[(c + 3) & 3], Ag, Bg, (c + 3) * BK, tid);
            cp_commit();
        }

        const uint32_t aBase = sA[s] + a_lane_off;
        const uint32_t bBase = sB[s] + b_lane_off;

        #pragma unroll
        for (int kt = 0; kt < 2; kt++) {
            uint32_t af[4][4], bf[8];
            #pragma unroll
            for (int mt = 0; mt < 4; mt++)
                ldsm_x4(af[mt][0], af[mt][1], af[mt][2], af[mt][3],
                        aBase + (uint32_t)(mt * 16 * A_STRIDE + kt * 32));
            // two x4.trans cover nt pairs {0,1} and {2,3}
            ldsm_x4t(bf[0], bf[1], bf[2], bf[3], bBase + (uint32_t)(kt * 16 * B_STRIDE));
            ldsm_x4t(bf[4], bf[5], bf[6], bf[7], bBase + (uint32_t)(kt * 16 * B_STRIDE + 32));
            #pragma unroll
            for (int mt = 0; mt < 4; mt++)
                #pragma unroll
                for (int nt = 0; nt < 4; nt++)
                    mma_bf16(acc[mt][nt], af[mt], &bf[nt * 2]);
        }
    }

    // ---- epilogue ----
    const int c0 = (lane & 3) * 2;
    const int r0 = lane >> 2;
    const float* bias_base = be + (size_t)e * Vn + v0 + wn * 32 + c0;

    float bias0[4], bias1[4];
    #pragma unroll
    for (int nt = 0; nt < 4; nt++) {
        bias0[nt] = bias_base[nt * 8];
        bias1[nt] = bias_base[nt * 8 + 1];
    }

    #pragma unroll
    for (int mt = 0; mt < 4; mt++) {
        const int row0 = t0 + wm * 64 + mt * 16 + r0;
        const int row1 = row0 + 8;
        const long long tg0 = tgt[(size_t)b * Tn + row0];
        const long long tg1 = tgt[(size_t)b * Tn + row1];
        float s0 = 0.0f, s1 = 0.0f;
        #pragma unroll
        for (int nt = 0; nt < 4; nt++) {
            const int v = v0 + wn * 32 + nt * 8 + c0;
            float l00 = acc[mt][nt][0] + bias0[nt];
            float l01 = acc[mt][nt][1] + bias1[nt];
            float l10 = acc[mt][nt][2] + bias0[nt];
            float l11 = acc[mt][nt][3] + bias1[nt];
            s0 += __expf(l00) + __expf(l01);
            s1 += __expf(l10) + __expf(l11);
            if ((long long)v     == tg0) g_tgt[(size_t)b * Tn + row0] = l00;
            if ((long long)(v+1) == tg0) g_tgt[(size_t)b * Tn + row0] = l01;
            if ((long long)v     == tg1) g_tgt[(size_t)b * Tn + row1] = l10;
            if ((long long)(v+1) == tg1) g_tgt[(size_t)b * Tn + row1] = l11;
        }
        s0 += __shfl_xor_sync(0xffffffffu, s0, 1);
        s0 += __shfl_xor_sync(0xffffffffu, s0, 2);
        s1 += __shfl_xor_sync(0xffffffffu, s1, 1);
        s1 += __shfl_xor_sync(0xffffffffu, s1, 2);
        if ((lane & 3) == 0) {
            atomicAdd(&g_sumexp[(size_t)b * Tn + row0], s0);
            atomicAdd(&g_sumexp[(size_t)b * Tn + row1], s1);
        }
    }
}

// ---------------- CE reductions ----------------
__global__ void ce_reduce_kernel()
{
    const int b = blockIdx.x;
    const int tid = threadIdx.x;
    float s = 0.0f;
    for (int t = tid; t < Tn; t += NTHREADS) {
        const int idx = b * Tn + t;
        s += logf(g_sumexp[idx]) - g_tgt[idx];
    }
    __shared__ float red[NTHREADS];
    red[tid] = s;
    __syncthreads();
    for (int off = NTHREADS / 2; off > 0; off >>= 1) {
        if (tid < off) red[tid] += red[tid + off];
        __syncthreads();
    }
    if (tid == 0) g_ce[b] = red[0] / (float)Tn;
}

__global__ void final_kernel(float* __restrict__ out)
{
    if (threadIdx.x == 0) {
        float sums[En], cnt[En];
        #pragma unroll
        for (int e = 0; e < En; e++) { sums[e] = 0.0f; cnt[e] = 0.0f; }
        for (int b = 0; b < Bn; b++) {
            sums[g_assign[b]] += g_ce[b];
            cnt[g_assign[b]]  += 1.0f;
        }
        float tot = 0.0f;
        #pragma unroll
        for (int e = 0; e < En; e++)
            if (cnt[e] > 0.0f) tot += sums[e] / cnt[e];
        out[0] = tot;
    }
}

// ---------------- launcher ----------------
extern "C" void kernel_launch(void* const* d_in, const int* in_sizes, int n_in,
                              void* d_out, int out_size)
{
    const float*     gate = (const float*)d_in[0];
    const float*     X    = (const float*)d_in[1];
    const float*     Wg   = (const float*)d_in[2];
    const float*     bg   = (const float*)d_in[3];
    const float*     We   = (const float*)d_in[4];
    const float*     be   = (const float*)d_in[5];
    const long long* tgt  = (const long long*)d_in[6];
    float* out = (float*)d_out;

    cudaFuncSetAttribute(gemm_ce_kernel, cudaFuncAttributeMaxDynamicSharedMemorySize, SMEM_BYTES);

    convert_x_kernel<<<((size_t)Bn * Tn * Dn / 4) / 256, 256>>>((const float4*)X);
    convert_w_kernel<<<((size_t)En * Dn * Vn / 4) / 256, 256>>>((const float4*)We);

    router_kernel<<<1, NTHREADS>>>(gate, Wg, bg, out, out_size);

    dim3 grid(Vn / BN, Tn / BM, Bn);
    gemm_ce_kernel<<<grid, GTHREADS, SMEM_BYTES>>>(be, tgt);

    ce_reduce_kernel<<<Bn, NTHREADS>>>();
    final_kernel<<<1, 32>>>(out);
}